// round 1
// baseline (speedup 1.0000x reference)
#include <cuda_runtime.h>
#include <math.h>

#define NTOK   8192
#define DMODEL 1024
#define DFFE   512
#define NEXP   16
#define DFFS   1024

// ---------------- scratch (device globals; no allocations) ----------------
__device__ int   d_cnt[NEXP];
__device__ int   d_lists[NEXP * NTOK];            // per-expert slot lists (slot = tok*2+k)
__device__ float d_gw[2 * NTOK];                  // gate weight per slot
__device__ float d_h[(size_t)2 * NTOK * DFFE];    // routed hidden, per slot   (32MB)
__device__ float d_ypart[(size_t)2 * NTOK * DMODEL]; // routed partial out per slot (64MB)
__device__ float d_hs[(size_t)NTOK * DFFS];       // shared hidden             (32MB)

__device__ __forceinline__ float fsigmoid(float v) { return 1.f / (1.f + __expf(-v)); }

#define STORE4(S, KK, ROW, PITCH, V)                                   \
    { (S)[((KK)+0)*(PITCH)+(ROW)] = (V).x; (S)[((KK)+1)*(PITCH)+(ROW)] = (V).y; \
      (S)[((KK)+2)*(PITCH)+(ROW)] = (V).z; (S)[((KK)+3)*(PITCH)+(ROW)] = (V).w; }

// ---------------- zero counters ----------------
__global__ void zero_cnt_kernel() {
    if (threadIdx.x < NEXP) d_cnt[threadIdx.x] = 0;
}

// ---------------- gate: one warp per token ----------------
__global__ void gate_kernel(const float* __restrict__ x,
                            const float* __restrict__ gw,
                            const float* __restrict__ ebias)
{
    int warp = (blockIdx.x * blockDim.x + threadIdx.x) >> 5;
    int lane = threadIdx.x & 31;
    if (warp >= NTOK) return;
    const float* xr = x + (size_t)warp * DMODEL;
    float xv[32];
#pragma unroll
    for (int j = 0; j < 32; j++) xv[j] = xr[lane + 32 * j];

    float logits[NEXP];
#pragma unroll
    for (int e = 0; e < NEXP; e++) {
        const float* wr = gw + e * DMODEL;
        float acc = 0.f;
#pragma unroll
        for (int j = 0; j < 32; j++) acc += xv[j] * wr[lane + 32 * j];
#pragma unroll
        for (int o = 16; o > 0; o >>= 1) acc += __shfl_xor_sync(0xffffffffu, acc, o);
        logits[e] = acc;
    }
    if (lane == 0) {
        int i0 = -1, i1 = -1;
        float v0 = -INFINITY, v1 = -INFINITY;
#pragma unroll
        for (int e = 0; e < NEXP; e++) {
            float b = logits[e] + ebias[e];
            if (b > v0) { v1 = v0; i1 = i0; v0 = b; i0 = e; }
            else if (b > v1) { v1 = b; i1 = e; }
        }
        float s0 = fsigmoid(logits[i0]);
        float s1 = fsigmoid(logits[i1]);
        float inv = 1.f / (s0 + s1 + 1e-10f);
        int p0 = atomicAdd(&d_cnt[i0], 1);
        d_lists[i0 * NTOK + p0] = warp * 2 + 0;
        d_gw[warp * 2 + 0] = s0 * inv;
        int p1 = atomicAdd(&d_cnt[i1], 1);
        d_lists[i1 * NTOK + p1] = warp * 2 + 1;
        d_gw[warp * 2 + 1] = s1 * inv;
    }
}

// ---------------- stage-1 dual NT-SGEMM: h = silu(X*W1^T+b1) * (X*W3^T+b3) ----------------
// tile BM=128, BN=64, BK=16, 256 threads, 8x4 per thread, dual accumulators
template<bool GATHER>
__global__ void ffn1_kernel(const float* __restrict__ X,
                            const float* __restrict__ W1b, const float* __restrict__ b1b,
                            const float* __restrict__ W3b, const float* __restrict__ b3b,
                            float* __restrict__ Hout,
                            int K, int Nout)
{
    const int BM = 128, BN = 64, BK = 16, PA = 132, PB = 68;
    int e  = blockIdx.z;
    int m0 = blockIdx.y * BM;
    int n0 = blockIdx.x * BN;
    int Mv = NTOK;
    const int* list = d_lists + e * NTOK;
    if (GATHER) {
        Mv = d_cnt[e];
        if (m0 >= Mv) return;
    }
    const float* W1 = W1b + (size_t)e * Nout * K;
    const float* W3 = W3b + (size_t)e * Nout * K;
    const float* b1 = b1b + e * Nout;
    const float* b3 = b3b + e * Nout;

    __shared__ float sA[2][BK * PA];
    __shared__ float sB1[2][BK * PB];
    __shared__ float sB3[2][BK * PB];
    __shared__ int   sslot[BM];

    int tid = threadIdx.x;
    if (tid < BM) {
        int m = m0 + tid;
        sslot[tid] = GATHER ? list[m < Mv ? m : Mv - 1] : m;
    }
    __syncthreads();

    int aRow0 = tid >> 2, aKK = (tid & 3) * 4;
    int aRow1 = aRow0 + 64;
    int t0 = sslot[aRow0]; if (GATHER) t0 >>= 1;
    int t1 = sslot[aRow1]; if (GATHER) t1 >>= 1;
    const float* aP0 = X + (size_t)t0 * DMODEL + aKK;
    const float* aP1 = X + (size_t)t1 * DMODEL + aKK;
    int bRow = tid >> 2;
    const float* p1 = W1 + (size_t)(n0 + bRow) * K + aKK;
    const float* p3 = W3 + (size_t)(n0 + bRow) * K + aKK;

    float acc1[8][4] = {}, acc3[8][4] = {};
    int ty = tid >> 4, tx = tid & 15;
    int ro = ty * 8, co = tx * 4;

    int ntiles = K / BK;
    float4 la0 = *(const float4*)aP0;
    float4 la1 = *(const float4*)aP1;
    float4 lb1 = *(const float4*)p1;
    float4 lb3 = *(const float4*)p3;
    STORE4(sA[0],  aKK, aRow0, PA, la0);
    STORE4(sA[0],  aKK, aRow1, PA, la1);
    STORE4(sB1[0], aKK, bRow,  PB, lb1);
    STORE4(sB3[0], aKK, bRow,  PB, lb3);
    __syncthreads();

    for (int t = 1; t <= ntiles; t++) {
        int cb = (t - 1) & 1;
        if (t < ntiles) {
            int k0 = t * BK;
            la0 = *(const float4*)(aP0 + k0);
            la1 = *(const float4*)(aP1 + k0);
            lb1 = *(const float4*)(p1 + k0);
            lb3 = *(const float4*)(p3 + k0);
        }
        const float* As  = sA[cb];
        const float* B1s = sB1[cb];
        const float* B3s = sB3[cb];
#pragma unroll
        for (int k = 0; k < BK; k++) {
            float4 a0 = *(const float4*)&As[k * PA + ro];
            float4 a1 = *(const float4*)&As[k * PA + ro + 4];
            float4 v1 = *(const float4*)&B1s[k * PB + co];
            float4 v3 = *(const float4*)&B3s[k * PB + co];
            float av[8]  = {a0.x, a0.y, a0.z, a0.w, a1.x, a1.y, a1.z, a1.w};
            float b1v[4] = {v1.x, v1.y, v1.z, v1.w};
            float b3v[4] = {v3.x, v3.y, v3.z, v3.w};
#pragma unroll
            for (int i = 0; i < 8; i++)
#pragma unroll
                for (int j = 0; j < 4; j++) {
                    acc1[i][j] += av[i] * b1v[j];
                    acc3[i][j] += av[i] * b3v[j];
                }
        }
        if (t < ntiles) {
            int sb = t & 1;
            STORE4(sA[sb],  aKK, aRow0, PA, la0);
            STORE4(sA[sb],  aKK, aRow1, PA, la1);
            STORE4(sB1[sb], aKK, bRow,  PB, lb1);
            STORE4(sB3[sb], aKK, bRow,  PB, lb3);
        }
        __syncthreads();
    }

    float bb1[4], bb3[4];
#pragma unroll
    for (int j = 0; j < 4; j++) { bb1[j] = b1[n0 + co + j]; bb3[j] = b3[n0 + co + j]; }
#pragma unroll
    for (int i = 0; i < 8; i++) {
        int m = m0 + ro + i;
        if (GATHER && m >= Mv) continue;
        int orow = sslot[ro + i];
        float* op = Hout + (size_t)orow * Nout + n0 + co;
#pragma unroll
        for (int j = 0; j < 4; j++) {
            float g = acc1[i][j] + bb1[j];
            float u = acc3[i][j] + bb3[j];
            op[j] = g * fsigmoid(g) * u;
        }
    }
}

// ---------------- stage-2 NT-SGEMM ----------------
// MODE 0: routed  — out[slot] = (H*W2^T + b2) * gate_w[slot]
// MODE 1: shared  — out[m]    =  Hs*sW2^T + sb2 + ypart[2m] + ypart[2m+1]
template<int MODE>
__global__ void ffn2_kernel(const float* __restrict__ Ain,
                            const float* __restrict__ Wb, const float* __restrict__ bb,
                            float* __restrict__ Out,
                            int K)
{
    const int BM = 128, BN = 128, BK = 16, PA = 132, PB = 132;
    int e  = blockIdx.z;
    int m0 = blockIdx.y * BM;
    int n0 = blockIdx.x * BN;
    int Mv = NTOK;
    const int* list = d_lists + e * NTOK;
    if (MODE == 0) {
        Mv = d_cnt[e];
        if (m0 >= Mv) return;
    }
    const float* W    = Wb + (size_t)e * DMODEL * K;
    const float* bias = bb + e * DMODEL;

    __shared__ float sA[2][BK * PA];
    __shared__ float sB[2][BK * PB];
    __shared__ int   sslot[BM];

    int tid = threadIdx.x;
    if (tid < BM) {
        int m = m0 + tid;
        sslot[tid] = (MODE == 0) ? list[m < Mv ? m : Mv - 1] : m;
    }
    __syncthreads();

    int aRow0 = tid >> 2, aKK = (tid & 3) * 4;
    int aRow1 = aRow0 + 64;
    const float* aP0 = Ain + (size_t)sslot[aRow0] * K + aKK;
    const float* aP1 = Ain + (size_t)sslot[aRow1] * K + aKK;
    const float* bP0 = W + (size_t)(n0 + aRow0) * K + aKK;
    const float* bP1 = W + (size_t)(n0 + aRow1) * K + aKK;

    float acc[8][8] = {};
    int ty = tid >> 4, tx = tid & 15;
    int ro = ty * 8, co = tx * 8;

    int ntiles = K / BK;
    float4 la0 = *(const float4*)aP0;
    float4 la1 = *(const float4*)aP1;
    float4 lb0 = *(const float4*)bP0;
    float4 lb1 = *(const float4*)bP1;
    STORE4(sA[0], aKK, aRow0, PA, la0);
    STORE4(sA[0], aKK, aRow1, PA, la1);
    STORE4(sB[0], aKK, aRow0, PB, lb0);
    STORE4(sB[0], aKK, aRow1, PB, lb1);
    __syncthreads();

    for (int t = 1; t <= ntiles; t++) {
        int cb = (t - 1) & 1;
        if (t < ntiles) {
            int k0 = t * BK;
            la0 = *(const float4*)(aP0 + k0);
            la1 = *(const float4*)(aP1 + k0);
            lb0 = *(const float4*)(bP0 + k0);
            lb1 = *(const float4*)(bP1 + k0);
        }
        const float* As = sA[cb];
        const float* Bs = sB[cb];
#pragma unroll
        for (int k = 0; k < BK; k++) {
            float4 a0 = *(const float4*)&As[k * PA + ro];
            float4 a1 = *(const float4*)&As[k * PA + ro + 4];
            float4 b0 = *(const float4*)&Bs[k * PB + co];
            float4 b1 = *(const float4*)&Bs[k * PB + co + 4];
            float av[8] = {a0.x, a0.y, a0.z, a0.w, a1.x, a1.y, a1.z, a1.w};
            float bv[8] = {b0.x, b0.y, b0.z, b0.w, b1.x, b1.y, b1.z, b1.w};
#pragma unroll
            for (int i = 0; i < 8; i++)
#pragma unroll
                for (int j = 0; j < 8; j++) acc[i][j] += av[i] * bv[j];
        }
        if (t < ntiles) {
            int sb = t & 1;
            STORE4(sA[sb], aKK, aRow0, PA, la0);
            STORE4(sA[sb], aKK, aRow1, PA, la1);
            STORE4(sB[sb], aKK, aRow0, PB, lb0);
            STORE4(sB[sb], aKK, aRow1, PB, lb1);
        }
        __syncthreads();
    }

    float bv[8];
#pragma unroll
    for (int j = 0; j < 8; j++) bv[j] = bias[n0 + co + j];

#pragma unroll
    for (int i = 0; i < 8; i++) {
        int m = m0 + ro + i;
        if (MODE == 0) {
            if (m >= Mv) continue;
            int slot = sslot[ro + i];
            float sc = d_gw[slot];
            float* op = Out + (size_t)slot * DMODEL + n0 + co;
#pragma unroll
            for (int j = 0; j < 8; j++) op[j] = (acc[i][j] + bv[j]) * sc;
        } else {
            const float* y0 = d_ypart + (size_t)(2 * m) * DMODEL + n0 + co;
            const float* y1 = y0 + DMODEL;
            float* op = Out + (size_t)m * DMODEL + n0 + co;
#pragma unroll
            for (int j = 0; j < 8; j++) op[j] = acc[i][j] + bv[j] + y0[j] + y1[j];
        }
    }
}

// ---------------- launch ----------------
extern "C" void kernel_launch(void* const* d_in, const int* in_sizes, int n_in,
                              void* d_out, int out_size)
{
    const float* x   = (const float*)d_in[0];
    const float* gw  = (const float*)d_in[1];
    const float* eb  = (const float*)d_in[2];
    const float* w1  = (const float*)d_in[3];
    const float* b1  = (const float*)d_in[4];
    const float* w3  = (const float*)d_in[5];
    const float* b3  = (const float*)d_in[6];
    const float* w2  = (const float*)d_in[7];
    const float* b2  = (const float*)d_in[8];
    const float* sw1 = (const float*)d_in[9];
    const float* sb1 = (const float*)d_in[10];
    const float* sw3 = (const float*)d_in[11];
    const float* sb3 = (const float*)d_in[12];
    const float* sw2 = (const float*)d_in[13];
    const float* sb2 = (const float*)d_in[14];
    float* out = (float*)d_out;

    float* h_ptr;  cudaGetSymbolAddress((void**)&h_ptr, d_h);
    float* yp_ptr; cudaGetSymbolAddress((void**)&yp_ptr, d_ypart);
    float* hs_ptr; cudaGetSymbolAddress((void**)&hs_ptr, d_hs);

    zero_cnt_kernel<<<1, 32>>>();
    gate_kernel<<<(NTOK * 32) / 256, 256>>>(x, gw, eb);

    // routed stage 1: per expert, gathered rows, N=512, K=1024
    ffn1_kernel<true><<<dim3(DFFE / 64, NTOK / 128, NEXP), 256>>>(
        x, w1, b1, w3, b3, h_ptr, DMODEL, DFFE);

    // shared stage 1: dense, N=1024, K=1024
    ffn1_kernel<false><<<dim3(DFFS / 64, NTOK / 128, 1), 256>>>(
        x, sw1, sb1, sw3, sb3, hs_ptr, DMODEL, DFFS);

    // routed stage 2: per expert, N=1024, K=512 -> ypart[slot]
    ffn2_kernel<0><<<dim3(DMODEL / 128, NTOK / 128, NEXP), 256>>>(
        h_ptr, w2, b2, yp_ptr, DFFE);

    // shared stage 2 + combine: N=1024, K=1024 -> out
    ffn2_kernel<1><<<dim3(DMODEL / 128, NTOK / 128, 1), 256>>>(
        hs_ptr, sw2, sb2, out, DFFS);
}

// round 3
// speedup vs baseline: 2.6397x; 2.6397x over previous
#include <cuda_runtime.h>
#include <cstdint>
#include <math.h>

#define NTOK   8192
#define DMODEL 1024
#define DFFE   512
#define NEXP   16
#define DFFS   1024

// ---------------- scratch (device globals; no allocations) ----------------
__device__ int   d_cnt[NEXP];
__device__ int   d_lists[NEXP * NTOK];               // per-expert slot lists (slot = tok*2+k)
__device__ float d_gw[2 * NTOK];                     // gate weight per slot
__device__ float d_h[(size_t)2 * NTOK * DFFE];       // routed hidden per slot
__device__ float d_ypart[(size_t)2 * NTOK * DMODEL]; // routed partial out per slot
__device__ float d_hs[(size_t)NTOK * DFFS];          // shared hidden

__device__ __forceinline__ float fsigmoid(float v) { return 1.f / (1.f + __expf(-v)); }
__device__ __forceinline__ uint32_t f2tf32(float f) {
    uint32_t u; asm("cvt.rna.tf32.f32 %0, %1;" : "=r"(u) : "f"(f)); return u;
}

__device__ __forceinline__ void mma_tf32(float* c, const uint32_t* a, uint32_t b0, uint32_t b1) {
    asm volatile("mma.sync.aligned.m16n8k8.row.col.f32.tf32.tf32.f32 "
        "{%0,%1,%2,%3}, {%4,%5,%6,%7}, {%8,%9}, {%0,%1,%2,%3};"
        : "+f"(c[0]), "+f"(c[1]), "+f"(c[2]), "+f"(c[3])
        : "r"(a[0]), "r"(a[1]), "r"(a[2]), "r"(a[3]), "r"(b0), "r"(b1));
}

// ---------------- smem layout ----------------
// pitch 36 floats per 32-float row (bank = lane for fragment LDS; conflict-free)
#define PITCH    36
#define BUFBYTES 18432              // 128 rows * 36 floats * 4B
#define ABUF_OFF 0                  // 2 buffers
#define BBUF_OFF (2 * BUFBYTES)     // 2 buffers
#define SLOT_OFF (4 * BUFBYTES)     // 73728: 128 ints
#define BIAS_OFF (SLOT_OFF + 512)   // 74240: 128 floats (or 64+64)
#define SMEM_TOTAL (BIAS_OFF + 1024) // 75264

__device__ __forceinline__ void sts_tf32(char* buf, uint32_t off, float4 v) {
    *(uint4*)(buf + off) = make_uint4(f2tf32(v.x), f2tf32(v.y), f2tf32(v.z), f2tf32(v.w));
}

// ---------------- zero counters ----------------
__global__ void zero_cnt_kernel() {
    if (threadIdx.x < NEXP) d_cnt[threadIdx.x] = 0;
}

// ---------------- gate: one warp per token ----------------
__global__ void gate_kernel(const float* __restrict__ x,
                            const float* __restrict__ gw,
                            const float* __restrict__ ebias)
{
    int warp = (blockIdx.x * blockDim.x + threadIdx.x) >> 5;
    int lane = threadIdx.x & 31;
    if (warp >= NTOK) return;
    const float* xr = x + (size_t)warp * DMODEL;
    float xv[32];
#pragma unroll
    for (int j = 0; j < 32; j++) xv[j] = xr[lane + 32 * j];
    float logits[NEXP];
#pragma unroll
    for (int e = 0; e < NEXP; e++) {
        const float* wr = gw + e * DMODEL;
        float acc = 0.f;
#pragma unroll
        for (int j = 0; j < 32; j++) acc += xv[j] * wr[lane + 32 * j];
#pragma unroll
        for (int o = 16; o > 0; o >>= 1) acc += __shfl_xor_sync(0xffffffffu, acc, o);
        logits[e] = acc;
    }
    if (lane == 0) {
        int i0 = -1, i1 = -1;
        float v0 = -INFINITY, v1 = -INFINITY;
#pragma unroll
        for (int e = 0; e < NEXP; e++) {
            float b = logits[e] + ebias[e];
            if (b > v0) { v1 = v0; i1 = i0; v0 = b; i0 = e; }
            else if (b > v1) { v1 = b; i1 = e; }
        }
        float s0 = fsigmoid(logits[i0]);
        float s1 = fsigmoid(logits[i1]);
        float inv = 1.f / (s0 + s1 + 1e-10f);
        int p0 = atomicAdd(&d_cnt[i0], 1);
        d_lists[i0 * NTOK + p0] = warp * 2 + 0;
        d_gw[warp * 2 + 0] = s0 * inv;
        int p1 = atomicAdd(&d_cnt[i1], 1);
        d_lists[i1 * NTOK + p1] = warp * 2 + 1;
        d_gw[warp * 2 + 1] = s1 * inv;
    }
}

// ---------------- stage-1: dual GEMM + SwiGLU via mma.sync tf32 ----------------
// CTA: 128 rows (tokens/slots) x 64 n of BOTH W1 and W3.
// B smem rows 0..63 = W1[n0..n0+63], rows 64..127 = W3[n0..n0+63].
// Warp (4m x 2n): 32 m-rows x 32 n (frag f<4 -> D1, f>=4 -> D3 of same n) -> fused SwiGLU.
template<bool GATHER>
__global__ void __launch_bounds__(256)
ffn1_mma(const float* __restrict__ X,
         const float* __restrict__ W1b, const float* __restrict__ b1b,
         const float* __restrict__ W3b, const float* __restrict__ b3b,
         float* __restrict__ Hout, int K, int Nout)
{
    int e  = blockIdx.z;
    int m0 = blockIdx.y * 128;
    int n0 = blockIdx.x * 64;
    int Mv = NTOK;
    const int* list = d_lists + e * NTOK;
    if (GATHER) { Mv = d_cnt[e]; if (m0 >= Mv) return; }
    const float* W1 = W1b + (size_t)e * Nout * K;
    const float* W3 = W3b + (size_t)e * Nout * K;

    extern __shared__ char smem[];
    int*   sslot = (int*)(smem + SLOT_OFF);
    float* sB1   = (float*)(smem + BIAS_OFF);
    float* sB3   = sB1 + 64;

    int tid = threadIdx.x;
    if (tid < 128) {
        int m = m0 + tid;
        sslot[tid] = GATHER ? list[m < Mv ? m : Mv - 1] : m;
    } else if (tid < 192) {
        int j = tid - 128;
        sB1[j] = b1b[e * Nout + n0 + j];
        sB3[j] = b3b[e * Nout + n0 + j];
    }
    __syncthreads();

    // loader: 4 float4 per thread per matrix per 128x32 tile
    const float* aSrc[4]; const float* bSrc[4]; uint32_t dstOff[4];
#pragma unroll
    for (int i = 0; i < 4; i++) {
        int idx = tid + i * 256;
        int row = idx >> 3, kq = idx & 7;
        int slot = sslot[row];
        int tr = GATHER ? (slot >> 1) : slot;
        aSrc[i] = X + (size_t)tr * K + kq * 4;
        bSrc[i] = (row < 64) ? (W1 + (size_t)(n0 + row) * K + kq * 4)
                             : (W3 + (size_t)(n0 + row - 64) * K + kq * 4);
        dstOff[i] = (uint32_t)(row * PITCH + kq * 4) * 4;
    }

    int wid = tid >> 5, lane = tid & 31;
    int wm = wid & 3, wn = wid >> 2;
    int lr = lane >> 2, lc = lane & 3;

    float acc[2][8][4] = {};

    int T = K / 32;
    float4 ra[4], rb[4];
#pragma unroll
    for (int i = 0; i < 4; i++) { ra[i] = *(const float4*)aSrc[i]; rb[i] = *(const float4*)bSrc[i]; }

    for (int t = 0; t < T; t++) {
        char* aB = smem + ABUF_OFF + (t & 1) * BUFBYTES;
        char* bB = smem + BBUF_OFF + (t & 1) * BUFBYTES;
#pragma unroll
        for (int i = 0; i < 4; i++) { sts_tf32(aB, dstOff[i], ra[i]); sts_tf32(bB, dstOff[i], rb[i]); }
        if (t + 1 < T) {
            int k0 = (t + 1) * 32;
#pragma unroll
            for (int i = 0; i < 4; i++) {
                ra[i] = *(const float4*)(aSrc[i] + k0);
                rb[i] = *(const float4*)(bSrc[i] + k0);
            }
        }
        __syncthreads();
        const uint32_t* A = (const uint32_t*)aB;
        const uint32_t* B = (const uint32_t*)bB;
#pragma unroll
        for (int kk = 0; kk < 4; kk++) {
            int k0 = kk * 8;
            uint32_t a[2][4];
#pragma unroll
            for (int mf = 0; mf < 2; mf++) {
                int r = wm * 32 + mf * 16 + lr;
                a[mf][0] = A[r * PITCH + k0 + lc];
                a[mf][1] = A[(r + 8) * PITCH + k0 + lc];
                a[mf][2] = A[r * PITCH + k0 + 4 + lc];
                a[mf][3] = A[(r + 8) * PITCH + k0 + 4 + lc];
            }
#pragma unroll
            for (int f = 0; f < 8; f++) {
                int br = (f < 4) ? (wn * 32 + 8 * f) : (64 + wn * 32 + 8 * (f - 4));
                uint32_t b0 = B[(br + lr) * PITCH + k0 + lc];
                uint32_t b1 = B[(br + lr) * PITCH + k0 + 4 + lc];
                mma_tf32(acc[0][f], a[0], b0, b1);
                mma_tf32(acc[1][f], a[1], b0, b1);
            }
        }
        __syncthreads();
    }

    // fused SwiGLU epilogue (D1 = frags 0..3, D3 = frags 4..7, same n)
#pragma unroll
    for (int mf = 0; mf < 2; mf++) {
#pragma unroll
        for (int f = 0; f < 4; f++) {
            int nb = wn * 32 + 8 * f + 2 * lc;
            float bg0 = sB1[nb], bg1 = sB1[nb + 1];
            float bu0 = sB3[nb], bu1 = sB3[nb + 1];
#pragma unroll
            for (int half = 0; half < 2; half++) {
                int rt = wm * 32 + mf * 16 + half * 8 + lr;
                int m = m0 + rt;
                if (GATHER && m >= Mv) continue;
                int orow = sslot[rt];
                float g0 = acc[mf][f][half * 2 + 0] + bg0;
                float g1 = acc[mf][f][half * 2 + 1] + bg1;
                float u0 = acc[mf][f + 4][half * 2 + 0] + bu0;
                float u1 = acc[mf][f + 4][half * 2 + 1] + bu1;
                float2 ov = make_float2(g0 * fsigmoid(g0) * u0, g1 * fsigmoid(g1) * u1);
                *(float2*)(Hout + (size_t)orow * Nout + n0 + nb) = ov;
            }
        }
    }
}

// ---------------- stage-2 GEMM via mma.sync tf32 ----------------
// MODE 0: routed  — ypart[slot] = (H[slot]*W2^T + b2) * d_gw[slot]
// MODE 1: shared  — out[m] = Hs[m]*sW2^T + sb2 + ypart[2m] + ypart[2m+1]
template<int MODE>
__global__ void __launch_bounds__(256)
ffn2_mma(const float* __restrict__ Ain,
         const float* __restrict__ Wb, const float* __restrict__ bb,
         float* __restrict__ Out, int K)
{
    int e  = blockIdx.z;
    int m0 = blockIdx.y * 128;
    int n0 = blockIdx.x * 128;
    int Mv = NTOK;
    const int* list = d_lists + e * NTOK;
    if (MODE == 0) { Mv = d_cnt[e]; if (m0 >= Mv) return; }
    const float* W = Wb + (size_t)e * DMODEL * K;

    extern __shared__ char smem[];
    int*   sslot = (int*)(smem + SLOT_OFF);
    float* sBB   = (float*)(smem + BIAS_OFF);

    int tid = threadIdx.x;
    if (tid < 128) {
        int m = m0 + tid;
        sslot[tid] = (MODE == 0) ? list[m < Mv ? m : Mv - 1] : m;
    } else {
        int j = tid - 128;
        sBB[j] = bb[e * DMODEL + n0 + j];
    }
    __syncthreads();

    const float* aSrc[4]; const float* bSrc[4]; uint32_t dstOff[4];
#pragma unroll
    for (int i = 0; i < 4; i++) {
        int idx = tid + i * 256;
        int row = idx >> 3, kq = idx & 7;
        aSrc[i] = Ain + (size_t)sslot[row] * K + kq * 4;
        bSrc[i] = W + (size_t)(n0 + row) * K + kq * 4;
        dstOff[i] = (uint32_t)(row * PITCH + kq * 4) * 4;
    }

    int wid = tid >> 5, lane = tid & 31;
    int wm = wid & 3, wn = wid >> 2;
    int lr = lane >> 2, lc = lane & 3;

    float acc[2][8][4] = {};

    int T = K / 32;
    float4 ra[4], rb[4];
#pragma unroll
    for (int i = 0; i < 4; i++) { ra[i] = *(const float4*)aSrc[i]; rb[i] = *(const float4*)bSrc[i]; }

    for (int t = 0; t < T; t++) {
        char* aB = smem + ABUF_OFF + (t & 1) * BUFBYTES;
        char* bB = smem + BBUF_OFF + (t & 1) * BUFBYTES;
#pragma unroll
        for (int i = 0; i < 4; i++) { sts_tf32(aB, dstOff[i], ra[i]); sts_tf32(bB, dstOff[i], rb[i]); }
        if (t + 1 < T) {
            int k0 = (t + 1) * 32;
#pragma unroll
            for (int i = 0; i < 4; i++) {
                ra[i] = *(const float4*)(aSrc[i] + k0);
                rb[i] = *(const float4*)(bSrc[i] + k0);
            }
        }
        __syncthreads();
        const uint32_t* A = (const uint32_t*)aB;
        const uint32_t* B = (const uint32_t*)bB;
#pragma unroll
        for (int kk = 0; kk < 4; kk++) {
            int k0 = kk * 8;
            uint32_t a[2][4];
#pragma unroll
            for (int mf = 0; mf < 2; mf++) {
                int r = wm * 32 + mf * 16 + lr;
                a[mf][0] = A[r * PITCH + k0 + lc];
                a[mf][1] = A[(r + 8) * PITCH + k0 + lc];
                a[mf][2] = A[r * PITCH + k0 + 4 + lc];
                a[mf][3] = A[(r + 8) * PITCH + k0 + 4 + lc];
            }
#pragma unroll
            for (int f = 0; f < 8; f++) {
                int br = wn * 64 + 8 * f;
                uint32_t b0 = B[(br + lr) * PITCH + k0 + lc];
                uint32_t b1 = B[(br + lr) * PITCH + k0 + 4 + lc];
                mma_tf32(acc[0][f], a[0], b0, b1);
                mma_tf32(acc[1][f], a[1], b0, b1);
            }
        }
        __syncthreads();
    }

#pragma unroll
    for (int mf = 0; mf < 2; mf++) {
#pragma unroll
        for (int half = 0; half < 2; half++) {
            int rt = wm * 32 + mf * 16 + half * 8 + lr;
            int m = m0 + rt;
            if (MODE == 0 && m >= Mv) continue;
            int orow = sslot[rt];
            float sc = (MODE == 0) ? d_gw[orow] : 0.f;
#pragma unroll
            for (int f = 0; f < 8; f++) {
                int nb = wn * 64 + 8 * f + 2 * lc;
                float c0 = acc[mf][f][half * 2 + 0] + sBB[nb];
                float c1 = acc[mf][f][half * 2 + 1] + sBB[nb + 1];
                if (MODE == 0) {
                    *(float2*)(d_ypart + (size_t)orow * DMODEL + n0 + nb) =
                        make_float2(c0 * sc, c1 * sc);
                } else {
                    const float* y0 = d_ypart + (size_t)(2 * m) * DMODEL + n0 + nb;
                    const float* y1 = y0 + DMODEL;
                    float2 a2 = *(const float2*)y0;
                    float2 b2 = *(const float2*)y1;
                    *(float2*)(Out + (size_t)m * DMODEL + n0 + nb) =
                        make_float2(c0 + a2.x + b2.x, c1 + a2.y + b2.y);
                }
            }
        }
    }
}

// ---------------- launch ----------------
extern "C" void kernel_launch(void* const* d_in, const int* in_sizes, int n_in,
                              void* d_out, int out_size)
{
    const float* x   = (const float*)d_in[0];
    const float* gw  = (const float*)d_in[1];
    const float* eb  = (const float*)d_in[2];
    const float* w1  = (const float*)d_in[3];
    const float* b1  = (const float*)d_in[4];
    const float* w3  = (const float*)d_in[5];
    const float* b3  = (const float*)d_in[6];
    const float* w2  = (const float*)d_in[7];
    const float* b2  = (const float*)d_in[8];
    const float* sw1 = (const float*)d_in[9];
    const float* sb1 = (const float*)d_in[10];
    const float* sw3 = (const float*)d_in[11];
    const float* sb3 = (const float*)d_in[12];
    const float* sw2 = (const float*)d_in[13];
    const float* sb2 = (const float*)d_in[14];
    float* out = (float*)d_out;

    float* h_ptr;  cudaGetSymbolAddress((void**)&h_ptr, d_h);
    float* yp_ptr; cudaGetSymbolAddress((void**)&yp_ptr, d_ypart);
    float* hs_ptr; cudaGetSymbolAddress((void**)&hs_ptr, d_hs);

    cudaFuncSetAttribute(ffn1_mma<true>,  cudaFuncAttributeMaxDynamicSharedMemorySize, SMEM_TOTAL);
    cudaFuncSetAttribute(ffn1_mma<false>, cudaFuncAttributeMaxDynamicSharedMemorySize, SMEM_TOTAL);
    cudaFuncSetAttribute(ffn2_mma<0>,     cudaFuncAttributeMaxDynamicSharedMemorySize, SMEM_TOTAL);
    cudaFuncSetAttribute(ffn2_mma<1>,     cudaFuncAttributeMaxDynamicSharedMemorySize, SMEM_TOTAL);

    zero_cnt_kernel<<<1, 32>>>();
    gate_kernel<<<(NTOK * 32) / 256, 256>>>(x, gw, eb);

    // routed stage 1: gathered, covers 64 n of W1+W3 per CTA; K=1024
    ffn1_mma<true><<<dim3(DFFE / 64, NTOK / 128, NEXP), 256, SMEM_TOTAL>>>(
        x, w1, b1, w3, b3, h_ptr, DMODEL, DFFE);

    // shared stage 1: dense; K=1024
    ffn1_mma<false><<<dim3(DFFS / 64, NTOK / 128, 1), 256, SMEM_TOTAL>>>(
        x, sw1, sb1, sw3, sb3, hs_ptr, DMODEL, DFFS);

    // routed stage 2: K=512 -> ypart[slot]
    ffn2_mma<0><<<dim3(DMODEL / 128, NTOK / 128, NEXP), 256, SMEM_TOTAL>>>(
        h_ptr, w2, b2, yp_ptr, DFFE);

    // shared stage 2 + combine: K=1024 -> out
    ffn2_mma<1><<<dim3(DMODEL / 128, NTOK / 128, 1), 256, SMEM_TOTAL>>>(
        hs_ptr, sw2, sb2, out, DFFS);
}

// round 4
// speedup vs baseline: 2.6906x; 1.0193x over previous
#include <cuda_runtime.h>
#include <cstdint>
#include <math.h>

#define NTOK   8192
#define DMODEL 1024
#define DFFE   512
#define NEXP   16
#define DFFS   1024

// ---------------- scratch (device globals; no allocations) ----------------
__device__ int   d_cnt[NEXP];
__device__ int   d_lists[NEXP * NTOK];               // per-expert slot lists (slot = tok*2+k)
__device__ float d_gw[2 * NTOK];                     // gate weight per slot
__device__ float d_h[(size_t)2 * NTOK * DFFE];       // routed hidden per slot
__device__ float d_ypart[(size_t)2 * NTOK * DMODEL]; // routed partial out per slot
__device__ float d_hs[(size_t)NTOK * DFFS];          // shared hidden

__device__ __forceinline__ float fsigmoid(float v) { return 1.f / (1.f + __expf(-v)); }
__device__ __forceinline__ uint32_t f2tf32(float f) {
    uint32_t u; asm("cvt.rna.tf32.f32 %0, %1;" : "=r"(u) : "f"(f)); return u;
}

__device__ __forceinline__ void mma_tf32(float* c, const uint32_t* a, uint32_t b0, uint32_t b1) {
    asm volatile("mma.sync.aligned.m16n8k8.row.col.f32.tf32.tf32.f32 "
        "{%0,%1,%2,%3}, {%4,%5,%6,%7}, {%8,%9}, {%0,%1,%2,%3};"
        : "+f"(c[0]), "+f"(c[1]), "+f"(c[2]), "+f"(c[3])
        : "r"(a[0]), "r"(a[1]), "r"(a[2]), "r"(a[3]), "r"(b0), "r"(b1));
}

// ---------------- smem layout ----------------
// BK = 16 k per tile; pitch 20 floats (20 mod 32 = 4*odd -> lr*20 mod 32 covers
// {0,20,8,28,16,4,24,12}: fragment LDS.32 is conflict-free)
#define BK       16
#define PITCH    20
#define BUFBYTES (128 * PITCH * 4)      // 10240
#define ABUF_OFF 0                      // 2 buffers
#define BBUF_OFF (2 * BUFBYTES)         // 2 buffers
#define SLOT_OFF (4 * BUFBYTES)         // 40960: 128 ints
#define BIAS_OFF (SLOT_OFF + 512)       // 41472: 128 floats
#define SMEM_TOTAL (BIAS_OFF + 1024)    // 42496

__device__ __forceinline__ void sts_tf32(char* buf, uint32_t off, float4 v) {
    *(uint4*)(buf + off) = make_uint4(f2tf32(v.x), f2tf32(v.y), f2tf32(v.z), f2tf32(v.w));
}

// ---------------- zero counters ----------------
__global__ void zero_cnt_kernel() {
    if (threadIdx.x < NEXP) d_cnt[threadIdx.x] = 0;
}

// ---------------- gate: one warp per token ----------------
__global__ void gate_kernel(const float* __restrict__ x,
                            const float* __restrict__ gw,
                            const float* __restrict__ ebias)
{
    int warp = (blockIdx.x * blockDim.x + threadIdx.x) >> 5;
    int lane = threadIdx.x & 31;
    if (warp >= NTOK) return;
    const float* xr = x + (size_t)warp * DMODEL;
    float xv[32];
#pragma unroll
    for (int j = 0; j < 32; j++) xv[j] = xr[lane + 32 * j];
    float logits[NEXP];
#pragma unroll
    for (int e = 0; e < NEXP; e++) {
        const float* wr = gw + e * DMODEL;
        float acc = 0.f;
#pragma unroll
        for (int j = 0; j < 32; j++) acc += xv[j] * wr[lane + 32 * j];
#pragma unroll
        for (int o = 16; o > 0; o >>= 1) acc += __shfl_xor_sync(0xffffffffu, acc, o);
        logits[e] = acc;
    }
    if (lane == 0) {
        int i0 = -1, i1 = -1;
        float v0 = -INFINITY, v1 = -INFINITY;
#pragma unroll
        for (int e = 0; e < NEXP; e++) {
            float b = logits[e] + ebias[e];
            if (b > v0) { v1 = v0; i1 = i0; v0 = b; i0 = e; }
            else if (b > v1) { v1 = b; i1 = e; }
        }
        float s0 = fsigmoid(logits[i0]);
        float s1 = fsigmoid(logits[i1]);
        float inv = 1.f / (s0 + s1 + 1e-10f);
        int p0 = atomicAdd(&d_cnt[i0], 1);
        d_lists[i0 * NTOK + p0] = warp * 2 + 0;
        d_gw[warp * 2 + 0] = s0 * inv;
        int p1 = atomicAdd(&d_cnt[i1], 1);
        d_lists[i1 * NTOK + p1] = warp * 2 + 1;
        d_gw[warp * 2 + 1] = s1 * inv;
    }
}

// ---------------- stage-1: dual GEMM + SwiGLU via mma.sync tf32 ----------------
// CTA: 128 rows x 64 n of BOTH W1 and W3 (B rows 0..63 = W1, 64..127 = W3).
// Warp (4m x 2n): 32 m-rows x 32 n; frag f<4 -> D1, f>=4 -> D3 of same n -> fused SwiGLU.
template<bool GATHER>
__global__ void __launch_bounds__(256, 2)
ffn1_mma(const float* __restrict__ X,
         const float* __restrict__ W1b, const float* __restrict__ b1b,
         const float* __restrict__ W3b, const float* __restrict__ b3b,
         float* __restrict__ Hout, int K, int Nout)
{
    int e  = blockIdx.z;
    int m0 = blockIdx.y * 128;
    int n0 = blockIdx.x * 64;
    int Mv = NTOK;
    const int* list = d_lists + e * NTOK;
    if (GATHER) { Mv = d_cnt[e]; if (m0 >= Mv) return; }
    const float* W1 = W1b + (size_t)e * Nout * K;
    const float* W3 = W3b + (size_t)e * Nout * K;

    extern __shared__ char smem[];
    int*   sslot = (int*)(smem + SLOT_OFF);
    float* sB1   = (float*)(smem + BIAS_OFF);
    float* sB3   = sB1 + 64;

    int tid = threadIdx.x;
    if (tid < 128) {
        int m = m0 + tid;
        sslot[tid] = GATHER ? list[m < Mv ? m : Mv - 1] : m;
    } else if (tid < 192) {
        int j = tid - 128;
        sB1[j] = b1b[e * Nout + n0 + j];
        sB3[j] = b3b[e * Nout + n0 + j];
    }
    __syncthreads();

    // loader: 2 float4 per thread per matrix per 128x16 tile
    const float* aSrc[2]; const float* bSrc[2]; uint32_t dstOff[2];
#pragma unroll
    for (int i = 0; i < 2; i++) {
        int idx = tid + i * 256;            // 0..511
        int row = idx >> 2, kq = idx & 3;
        int slot = sslot[row];
        int tr = GATHER ? (slot >> 1) : slot;
        aSrc[i] = X + (size_t)tr * K + kq * 4;
        bSrc[i] = (row < 64) ? (W1 + (size_t)(n0 + row) * K + kq * 4)
                             : (W3 + (size_t)(n0 + row - 64) * K + kq * 4);
        dstOff[i] = (uint32_t)(row * PITCH + kq * 4) * 4;
    }

    int wid = tid >> 5, lane = tid & 31;
    int wm = wid & 3, wn = wid >> 2;
    int lr = lane >> 2, lc = lane & 3;

    float acc[2][8][4] = {};

    int T = K / BK;
    float4 ra[2], rb[2];
#pragma unroll
    for (int i = 0; i < 2; i++) { ra[i] = *(const float4*)aSrc[i]; rb[i] = *(const float4*)bSrc[i]; }

    for (int t = 0; t < T; t++) {
        char* aB = smem + ABUF_OFF + (t & 1) * BUFBYTES;
        char* bB = smem + BBUF_OFF + (t & 1) * BUFBYTES;
#pragma unroll
        for (int i = 0; i < 2; i++) { sts_tf32(aB, dstOff[i], ra[i]); sts_tf32(bB, dstOff[i], rb[i]); }
        if (t + 1 < T) {
            int k0 = (t + 1) * BK;
#pragma unroll
            for (int i = 0; i < 2; i++) {
                ra[i] = *(const float4*)(aSrc[i] + k0);
                rb[i] = *(const float4*)(bSrc[i] + k0);
            }
        }
        __syncthreads();
        const uint32_t* A = (const uint32_t*)aB;
        const uint32_t* B = (const uint32_t*)bB;
#pragma unroll
        for (int kk = 0; kk < 2; kk++) {
            int k0 = kk * 8;
            uint32_t a[2][4];
#pragma unroll
            for (int mf = 0; mf < 2; mf++) {
                int r = wm * 32 + mf * 16 + lr;
                a[mf][0] = A[r * PITCH + k0 + lc];
                a[mf][1] = A[(r + 8) * PITCH + k0 + lc];
                a[mf][2] = A[r * PITCH + k0 + 4 + lc];
                a[mf][3] = A[(r + 8) * PITCH + k0 + 4 + lc];
            }
#pragma unroll
            for (int f = 0; f < 8; f++) {
                int br = (f < 4) ? (wn * 32 + 8 * f) : (64 + wn * 32 + 8 * (f - 4));
                uint32_t b0 = B[(br + lr) * PITCH + k0 + lc];
                uint32_t b1 = B[(br + lr) * PITCH + k0 + 4 + lc];
                mma_tf32(acc[0][f], a[0], b0, b1);
                mma_tf32(acc[1][f], a[1], b0, b1);
            }
        }
        __syncthreads();
    }

    // fused SwiGLU epilogue (D1 = frags 0..3, D3 = frags 4..7, same n)
#pragma unroll
    for (int mf = 0; mf < 2; mf++) {
#pragma unroll
        for (int f = 0; f < 4; f++) {
            int nb = wn * 32 + 8 * f + 2 * lc;
            float bg0 = sB1[nb], bg1 = sB1[nb + 1];
            float bu0 = sB3[nb], bu1 = sB3[nb + 1];
#pragma unroll
            for (int half = 0; half < 2; half++) {
                int rt = wm * 32 + mf * 16 + half * 8 + lr;
                int m = m0 + rt;
                if (GATHER && m >= Mv) continue;
                int orow = sslot[rt];
                float g0 = acc[mf][f][half * 2 + 0] + bg0;
                float g1 = acc[mf][f][half * 2 + 1] + bg1;
                float u0 = acc[mf][f + 4][half * 2 + 0] + bu0;
                float u1 = acc[mf][f + 4][half * 2 + 1] + bu1;
                float2 ov = make_float2(g0 * fsigmoid(g0) * u0, g1 * fsigmoid(g1) * u1);
                *(float2*)(Hout + (size_t)orow * Nout + n0 + nb) = ov;
            }
        }
    }
}

// ---------------- stage-2 GEMM via mma.sync tf32 ----------------
// MODE 0: routed  — ypart[slot] = (H[slot]*W2^T + b2) * d_gw[slot]
// MODE 1: shared  — out[m] = Hs[m]*sW2^T + sb2 + ypart[2m] + ypart[2m+1]
template<int MODE>
__global__ void __launch_bounds__(256, 2)
ffn2_mma(const float* __restrict__ Ain,
         const float* __restrict__ Wb, const float* __restrict__ bb,
         float* __restrict__ Out, int K)
{
    int e  = blockIdx.z;
    int m0 = blockIdx.y * 128;
    int n0 = blockIdx.x * 128;
    int Mv = NTOK;
    const int* list = d_lists + e * NTOK;
    if (MODE == 0) { Mv = d_cnt[e]; if (m0 >= Mv) return; }
    const float* W = Wb + (size_t)e * DMODEL * K;

    extern __shared__ char smem[];
    int*   sslot = (int*)(smem + SLOT_OFF);
    float* sBB   = (float*)(smem + BIAS_OFF);

    int tid = threadIdx.x;
    if (tid < 128) {
        int m = m0 + tid;
        sslot[tid] = (MODE == 0) ? list[m < Mv ? m : Mv - 1] : m;
    } else {
        int j = tid - 128;
        sBB[j] = bb[e * DMODEL + n0 + j];
    }
    __syncthreads();

    const float* aSrc[2]; const float* bSrc[2]; uint32_t dstOff[2];
#pragma unroll
    for (int i = 0; i < 2; i++) {
        int idx = tid + i * 256;
        int row = idx >> 2, kq = idx & 3;
        aSrc[i] = Ain + (size_t)sslot[row] * K + kq * 4;
        bSrc[i] = W + (size_t)(n0 + row) * K + kq * 4;
        dstOff[i] = (uint32_t)(row * PITCH + kq * 4) * 4;
    }

    int wid = tid >> 5, lane = tid & 31;
    int wm = wid & 3, wn = wid >> 2;
    int lr = lane >> 2, lc = lane & 3;

    float acc[2][8][4] = {};

    int T = K / BK;
    float4 ra[2], rb[2];
#pragma unroll
    for (int i = 0; i < 2; i++) { ra[i] = *(const float4*)aSrc[i]; rb[i] = *(const float4*)bSrc[i]; }

    for (int t = 0; t < T; t++) {
        char* aB = smem + ABUF_OFF + (t & 1) * BUFBYTES;
        char* bB = smem + BBUF_OFF + (t & 1) * BUFBYTES;
#pragma unroll
        for (int i = 0; i < 2; i++) { sts_tf32(aB, dstOff[i], ra[i]); sts_tf32(bB, dstOff[i], rb[i]); }
        if (t + 1 < T) {
            int k0 = (t + 1) * BK;
#pragma unroll
            for (int i = 0; i < 2; i++) {
                ra[i] = *(const float4*)(aSrc[i] + k0);
                rb[i] = *(const float4*)(bSrc[i] + k0);
            }
        }
        __syncthreads();
        const uint32_t* A = (const uint32_t*)aB;
        const uint32_t* B = (const uint32_t*)bB;
#pragma unroll
        for (int kk = 0; kk < 2; kk++) {
            int k0 = kk * 8;
            uint32_t a[2][4];
#pragma unroll
            for (int mf = 0; mf < 2; mf++) {
                int r = wm * 32 + mf * 16 + lr;
                a[mf][0] = A[r * PITCH + k0 + lc];
                a[mf][1] = A[(r + 8) * PITCH + k0 + lc];
                a[mf][2] = A[r * PITCH + k0 + 4 + lc];
                a[mf][3] = A[(r + 8) * PITCH + k0 + 4 + lc];
            }
#pragma unroll
            for (int f = 0; f < 8; f++) {
                int br = wn * 64 + 8 * f;
                uint32_t b0 = B[(br + lr) * PITCH + k0 + lc];
                uint32_t b1 = B[(br + lr) * PITCH + k0 + 4 + lc];
                mma_tf32(acc[0][f], a[0], b0, b1);
                mma_tf32(acc[1][f], a[1], b0, b1);
            }
        }
        __syncthreads();
    }

#pragma unroll
    for (int mf = 0; mf < 2; mf++) {
#pragma unroll
        for (int half = 0; half < 2; half++) {
            int rt = wm * 32 + mf * 16 + half * 8 + lr;
            int m = m0 + rt;
            if (MODE == 0 && m >= Mv) continue;
            int orow = sslot[rt];
            float sc = (MODE == 0) ? d_gw[orow] : 0.f;
#pragma unroll
            for (int f = 0; f < 8; f++) {
                int nb = wn * 64 + 8 * f + 2 * lc;
                float c0 = acc[mf][f][half * 2 + 0] + sBB[nb];
                float c1 = acc[mf][f][half * 2 + 1] + sBB[nb + 1];
                if (MODE == 0) {
                    *(float2*)(d_ypart + (size_t)orow * DMODEL + n0 + nb) =
                        make_float2(c0 * sc, c1 * sc);
                } else {
                    const float* y0 = d_ypart + (size_t)(2 * m) * DMODEL + n0 + nb;
                    const float* y1 = y0 + DMODEL;
                    float2 a2 = *(const float2*)y0;
                    float2 b2 = *(const float2*)y1;
                    *(float2*)(Out + (size_t)m * DMODEL + n0 + nb) =
                        make_float2(c0 + a2.x + b2.x, c1 + a2.y + b2.y);
                }
            }
        }
    }
}

// ---------------- launch ----------------
extern "C" void kernel_launch(void* const* d_in, const int* in_sizes, int n_in,
                              void* d_out, int out_size)
{
    const float* x   = (const float*)d_in[0];
    const float* gw  = (const float*)d_in[1];
    const float* eb  = (const float*)d_in[2];
    const float* w1  = (const float*)d_in[3];
    const float* b1  = (const float*)d_in[4];
    const float* w3  = (const float*)d_in[5];
    const float* b3  = (const float*)d_in[6];
    const float* w2  = (const float*)d_in[7];
    const float* b2  = (const float*)d_in[8];
    const float* sw1 = (const float*)d_in[9];
    const float* sb1 = (const float*)d_in[10];
    const float* sw3 = (const float*)d_in[11];
    const float* sb3 = (const float*)d_in[12];
    const float* sw2 = (const float*)d_in[13];
    const float* sb2 = (const float*)d_in[14];
    float* out = (float*)d_out;

    float* h_ptr;  cudaGetSymbolAddress((void**)&h_ptr, d_h);
    float* yp_ptr; cudaGetSymbolAddress((void**)&yp_ptr, d_ypart);
    float* hs_ptr; cudaGetSymbolAddress((void**)&hs_ptr, d_hs);

    cudaFuncSetAttribute(ffn1_mma<true>,  cudaFuncAttributeMaxDynamicSharedMemorySize, SMEM_TOTAL);
    cudaFuncSetAttribute(ffn1_mma<false>, cudaFuncAttributeMaxDynamicSharedMemorySize, SMEM_TOTAL);
    cudaFuncSetAttribute(ffn2_mma<0>,     cudaFuncAttributeMaxDynamicSharedMemorySize, SMEM_TOTAL);
    cudaFuncSetAttribute(ffn2_mma<1>,     cudaFuncAttributeMaxDynamicSharedMemorySize, SMEM_TOTAL);

    zero_cnt_kernel<<<1, 32>>>();
    gate_kernel<<<(NTOK * 32) / 256, 256>>>(x, gw, eb);

    // routed stage 1: gathered, 64 n of W1+W3 per CTA; K=1024
    ffn1_mma<true><<<dim3(DFFE / 64, NTOK / 128, NEXP), 256, SMEM_TOTAL>>>(
        x, w1, b1, w3, b3, h_ptr, DMODEL, DFFE);

    // shared stage 1: dense; K=1024
    ffn1_mma<false><<<dim3(DFFS / 64, NTOK / 128, 1), 256, SMEM_TOTAL>>>(
        x, sw1, sb1, sw3, sb3, hs_ptr, DMODEL, DFFS);

    // routed stage 2: K=512 -> ypart[slot]
    ffn2_mma<0><<<dim3(DMODEL / 128, NTOK / 128, NEXP), 256, SMEM_TOTAL>>>(
        h_ptr, w2, b2, yp_ptr, DFFE);

    // shared stage 2 + combine: K=1024 -> out
    ffn2_mma<1><<<dim3(DMODEL / 128, NTOK / 128, 1), 256, SMEM_TOTAL>>>(
        hs_ptr, sw2, sb2, out, DFFS);
}